// round 6
// baseline (speedup 1.0000x reference)
#include <cuda_runtime.h>
#include <math.h>

#define NN 50000
#define NE 800000
#define NG 64
#define SLOT 96

typedef unsigned long long u64;
typedef unsigned int u32;

// ------------------- scratch (device globals; zero-initialized at load) ----
__device__ float d_xl1[NN * 256];
__device__ float d_h1 [NN * 256];
__device__ float d_xl2[NN * 128];
__device__ float d_xr2[NN * 128];
__device__ float d_h2 [NN * 128];
__device__ float d_loopsum[NN];
__device__ int   d_cursor[NN];
__device__ u64   d_sadj[(size_t)NN * SLOT];   // packed (ea:f32 hi, src:i32 lo)
__device__ float d_pool[NG * 128];
__device__ float d_cnt[NG];

// ---------------------------------------------------------------------------
// adjacency fill (half range per launch): slot table keyed by dst
__global__ void k_fill(const int* __restrict__ ei, const float* __restrict__ ea,
                       int e0, int e1) {
    int e = e0 + blockIdx.x * 256 + threadIdx.x;
    if (e < e1) {
        int dst = ei[NE + e];
        int src = ei[e];
        float v = ea[e];
        int p = atomicAdd(&d_cursor[dst], 1);
        if (p < SLOT)
            d_sadj[(size_t)dst * SLOT + p] =
                ((u64)__float_as_uint(v) << 32) | (u32)src;
        atomicAdd(&d_loopsum[dst], v);
    }
}

// xl1 = x @ Wl1 (K=8). 4 nodes per block, 256 threads (thread = column).
__global__ void k_gemm1(const float* __restrict__ x, const float* __restrict__ Wl) {
    __shared__ float sx[32];
    int n0 = blockIdx.x * 4;
    int tid = threadIdx.x;
    if (tid < 32) sx[tid] = x[n0 * 8 + tid];
    __syncthreads();
    float w[8];
#pragma unroll
    for (int k = 0; k < 8; k++) w[k] = Wl[k * 256 + tid];
#pragma unroll
    for (int q = 0; q < 4; q++) {
        float a = 0.f;
#pragma unroll
        for (int k = 0; k < 8; k++) a += sx[q * 8 + k] * w[k];
        d_xl1[(size_t)(n0 + q) * 256 + tid] = a;
    }
}

__device__ __forceinline__ float gat_term(float l, float r, float w, float at, float eav) {
    float m = l + r + eav * w;
    m = (m > 0.f) ? m : 0.2f * m;
    return m * at;
}

// ======== layer-1 FUSED, warp per node, software-pipelined ==================
__global__ __launch_bounds__(256) void
k_fagg1(const float* __restrict__ x,
        const float* __restrict__ Wr, const float* __restrict__ We,
        const float* __restrict__ att,
        const float* __restrict__ b1, const float* __restrict__ g1,
        const float* __restrict__ beta1) {
    int wid = threadIdx.x >> 5, lane = threadIdx.x & 31;
    int n = blockIdx.x * 8 + wid;
    if (n >= NN) return;

    int cnt = d_cursor[n];
    if (cnt > SLOT) cnt = SLOT;
    float loopv = d_loopsum[n] / fmaxf((float)cnt, 1.f);

    int cA = lane * 4;
    int cB = 128 + lane * 4;

    // xr row: x[n] (8) @ Wr (8x256), this lane's 8 channels
    float xv = (lane < 8) ? x[n * 8 + lane] : 0.f;
    float xrA[4] = {0.f, 0.f, 0.f, 0.f}, xrB[4] = {0.f, 0.f, 0.f, 0.f};
#pragma unroll
    for (int k = 0; k < 8; k++) {
        float xk = __shfl_sync(0xffffffffu, xv, k);
        float4 wA = __ldg((const float4*)(Wr + k * 256 + cA));
        float4 wB = __ldg((const float4*)(Wr + k * 256 + cB));
        xrA[0] += xk * wA.x; xrA[1] += xk * wA.y; xrA[2] += xk * wA.z; xrA[3] += xk * wA.w;
        xrB[0] += xk * wB.x; xrB[1] += xk * wB.y; xrB[2] += xk * wB.z; xrB[3] += xk * wB.w;
    }
    float4 weA = __ldg((const float4*)(We + cA));
    float4 weB = __ldg((const float4*)(We + cB));
    float4 atA = __ldg((const float4*)(att + cA));
    float4 atB = __ldg((const float4*)(att + cB));

    float mA = -1e30f, dA = 0.f, mB = -1e30f, dB = 0.f;
    float accA[4] = {0.f, 0.f, 0.f, 0.f}, accB[4] = {0.f, 0.f, 0.f, 0.f};

    const size_t sbase = (size_t)n * SLOT;
    // prefetch iteration 0
    int srcN; float eaN;
    if (cnt > 0) {
        u64 p = d_sadj[sbase];
        srcN = (int)(u32)p; eaN = __uint_as_float((u32)(p >> 32));
    } else { srcN = n; eaN = loopv; }
    float4 lA_n = *(const float4*)(d_xl1 + (size_t)srcN * 256 + cA);
    float4 lB_n = *(const float4*)(d_xl1 + (size_t)srcN * 256 + cB);
    float eav_n = eaN;

    for (int i = 0; i <= cnt; i++) {
        float4 lA = lA_n, lB = lB_n;
        float eav = eav_n;
        // prefetch next edge (gather issues before the shfl/exp chain below)
        int j = i + 1;
        if (j <= cnt) {
            int s2; float e2;
            if (j < cnt) {
                u64 p = d_sadj[sbase + j];
                s2 = (int)(u32)p; e2 = __uint_as_float((u32)(p >> 32));
            } else { s2 = n; e2 = loopv; }
            lA_n = *(const float4*)(d_xl1 + (size_t)s2 * 256 + cA);
            lB_n = *(const float4*)(d_xl1 + (size_t)s2 * 256 + cB);
            eav_n = e2;
        }

        float a = 0.f, b = 0.f;
        a += gat_term(lA.x, xrA[0], weA.x, atA.x, eav);
        a += gat_term(lA.y, xrA[1], weA.y, atA.y, eav);
        a += gat_term(lA.z, xrA[2], weA.z, atA.z, eav);
        a += gat_term(lA.w, xrA[3], weA.w, atA.w, eav);
        b += gat_term(lB.x, xrB[0], weB.x, atB.x, eav);
        b += gat_term(lB.y, xrB[1], weB.y, atB.y, eav);
        b += gat_term(lB.z, xrB[2], weB.z, atB.z, eav);
        b += gat_term(lB.w, xrB[3], weB.w, atB.w, eav);
        // 16-lane segmented sums -> per-head logits (2 heads per lane)
#pragma unroll
        for (int d = 1; d < 16; d <<= 1) {
            a += __shfl_xor_sync(0xffffffffu, a, d);
            b += __shfl_xor_sync(0xffffffffu, b, d);
        }
        // online softmax, head A
        float nmA = fmaxf(mA, a);
        float scA = __expf(mA - nmA);
        float eA  = __expf(a - nmA);
        dA = dA * scA + eA; mA = nmA;
        accA[0] = accA[0] * scA + eA * lA.x;
        accA[1] = accA[1] * scA + eA * lA.y;
        accA[2] = accA[2] * scA + eA * lA.z;
        accA[3] = accA[3] * scA + eA * lA.w;
        // head B
        float nmB = fmaxf(mB, b);
        float scB = __expf(mB - nmB);
        float eB  = __expf(b - nmB);
        dB = dB * scB + eB; mB = nmB;
        accB[0] = accB[0] * scB + eB * lB.x;
        accB[1] = accB[1] * scB + eB * lB.y;
        accB[2] = accB[2] * scB + eB * lB.z;
        accB[3] = accB[3] * scB + eB * lB.w;
    }

    float invA = 1.f / (dA + 1e-16f);
    float invB = 1.f / (dB + 1e-16f);
    float4 bA = __ldg((const float4*)(b1 + cA));
    float4 bBv = __ldg((const float4*)(b1 + cB));
    float oA[4], oB[4];
    oA[0] = accA[0] * invA + bA.x; oA[1] = accA[1] * invA + bA.y;
    oA[2] = accA[2] * invA + bA.z; oA[3] = accA[3] * invA + bA.w;
    oB[0] = accB[0] * invB + bBv.x; oB[1] = accB[1] * invB + bBv.y;
    oB[2] = accB[2] * invB + bBv.z; oB[3] = accB[3] * invB + bBv.w;

    // LayerNorm(256) across the warp
    float s = 0.f, s2 = 0.f;
#pragma unroll
    for (int j = 0; j < 4; j++) {
        s += oA[j] + oB[j];
        s2 += oA[j] * oA[j] + oB[j] * oB[j];
    }
#pragma unroll
    for (int d = 16; d >= 1; d >>= 1) {
        s  += __shfl_xor_sync(0xffffffffu, s, d);
        s2 += __shfl_xor_sync(0xffffffffu, s2, d);
    }
    float mu = s * (1.f / 256.f);
    float var = s2 * (1.f / 256.f) - mu * mu;
    float rstd = rsqrtf(var + 1e-5f);
    float4 gA = __ldg((const float4*)(g1 + cA));
    float4 gB = __ldg((const float4*)(g1 + cB));
    float4 tA = __ldg((const float4*)(beta1 + cA));
    float4 tB = __ldg((const float4*)(beta1 + cB));
    float yA[4], yB[4];
    yA[0] = (oA[0]-mu)*rstd*gA.x + tA.x; yA[1] = (oA[1]-mu)*rstd*gA.y + tA.y;
    yA[2] = (oA[2]-mu)*rstd*gA.z + tA.z; yA[3] = (oA[3]-mu)*rstd*gA.w + tA.w;
    yB[0] = (oB[0]-mu)*rstd*gB.x + tB.x; yB[1] = (oB[1]-mu)*rstd*gB.y + tB.y;
    yB[2] = (oB[2]-mu)*rstd*gB.z + tB.z; yB[3] = (oB[3]-mu)*rstd*gB.w + tB.w;
#pragma unroll
    for (int j = 0; j < 4; j++) {
        yA[j] = (yA[j] > 0.f) ? yA[j] : (__expf(yA[j]) - 1.f);
        yB[j] = (yB[j] > 0.f) ? yB[j] : (__expf(yB[j]) - 1.f);
    }
    *(float4*)(d_h1 + (size_t)n * 256 + cA) = make_float4(yA[0], yA[1], yA[2], yA[3]);
    *(float4*)(d_h1 + (size_t)n * 256 + cB) = make_float4(yB[0], yB[1], yB[2], yB[3]);
}

// ======== GEMM2 via tf32 mma.sync m16n8k8: [xl2|xr2] = h1 @ [Wl2|Wr2] =======
__device__ __forceinline__ u32 f2tf(float f) {
    u32 u;
    asm("cvt.rna.tf32.f32 %0, %1;" : "=r"(u) : "f"(f));
    return u;
}
__device__ __forceinline__ void mma_tf32(float* d, const u32* a, u32 b0, u32 b1) {
    asm("mma.sync.aligned.m16n8k8.row.col.f32.tf32.tf32.f32 "
        "{%0,%1,%2,%3}, {%4,%5,%6,%7}, {%8,%9}, {%0,%1,%2,%3};"
        : "+f"(d[0]), "+f"(d[1]), "+f"(d[2]), "+f"(d[3])
        : "r"(a[0]), "r"(a[1]), "r"(a[2]), "r"(a[3]), "r"(b0), "r"(b1));
}

// grid: ceil(NN/128) blocks x 512 threads (16 warps).
// block tile: 128 nodes x 256 out-cols (0-127 -> xl2 via Wl2, 128-255 -> xr2 via Wr2)
// warp w: mgrp = w>>2 -> rows [mgrp*32,+32); ngrp = w&3 -> cols [ngrp*64,+64)
__global__ __launch_bounds__(512) void
k_gemm2(const float* __restrict__ Wl, const float* __restrict__ Wr) {
    int w = threadIdx.x >> 5, lane = threadIdx.x & 31;
    int gid = lane >> 2, tig = lane & 3;
    int mgrp = w >> 2, ngrp = w & 3;
    int row0 = blockIdx.x * 128 + mgrp * 32;
    int colbase = ngrp * 64;
    const float* W = (colbase < 128) ? Wl : Wr;
    float* OUT = (colbase < 128) ? d_xl2 : d_xr2;
    int wcol = colbase & 127;

    float d[2][8][4];
#pragma unroll
    for (int mt = 0; mt < 2; mt++)
#pragma unroll
        for (int nt = 0; nt < 8; nt++)
#pragma unroll
            for (int q = 0; q < 4; q++) d[mt][nt][q] = 0.f;

    // clamped rows for A loads (stores are guarded)
    int r0a = row0 + gid,       r0b = r0a + 8;
    int r1a = row0 + 16 + gid,  r1b = r1a + 8;
    r0a = min(r0a, NN - 1); r0b = min(r0b, NN - 1);
    r1a = min(r1a, NN - 1); r1b = min(r1b, NN - 1);
    const float* h0a = d_h1 + (size_t)r0a * 256;
    const float* h0b = d_h1 + (size_t)r0b * 256;
    const float* h1a = d_h1 + (size_t)r1a * 256;
    const float* h1b = d_h1 + (size_t)r1b * 256;

    for (int k0 = 0; k0 < 256; k0 += 8) {
        u32 a[2][4];
        a[0][0] = f2tf(h0a[k0 + tig]);
        a[0][1] = f2tf(h0b[k0 + tig]);
        a[0][2] = f2tf(h0a[k0 + tig + 4]);
        a[0][3] = f2tf(h0b[k0 + tig + 4]);
        a[1][0] = f2tf(h1a[k0 + tig]);
        a[1][1] = f2tf(h1b[k0 + tig]);
        a[1][2] = f2tf(h1a[k0 + tig + 4]);
        a[1][3] = f2tf(h1b[k0 + tig + 4]);
#pragma unroll
        for (int nt = 0; nt < 8; nt++) {
            int c = wcol + nt * 8 + gid;
            u32 b0 = f2tf(__ldg(W + (size_t)(k0 + tig) * 128 + c));
            u32 b1 = f2tf(__ldg(W + (size_t)(k0 + tig + 4) * 128 + c));
            mma_tf32(d[0][nt], a[0], b0, b1);
            mma_tf32(d[1][nt], a[1], b0, b1);
        }
    }

    // epilogue: c0:(g,2t) c1:(g,2t+1) c2:(g+8,2t) c3:(g+8,2t+1)
#pragma unroll
    for (int mt = 0; mt < 2; mt++) {
        int rA = row0 + mt * 16 + gid;
        int rB = rA + 8;
#pragma unroll
        for (int nt = 0; nt < 8; nt++) {
            int cg = wcol + nt * 8 + 2 * tig;
            if (rA < NN)
                *(float2*)(OUT + (size_t)rA * 128 + cg) = make_float2(d[mt][nt][0], d[mt][nt][1]);
            if (rB < NN)
                *(float2*)(OUT + (size_t)rB * 128 + cg) = make_float2(d[mt][nt][2], d[mt][nt][3]);
        }
    }
}

// ======== layer-2 FUSED, warp per node, software-pipelined ==================
__global__ __launch_bounds__(256) void
k_fagg2(const float* __restrict__ We, const float* __restrict__ att,
        const float* __restrict__ b2, const float* __restrict__ g2,
        const float* __restrict__ beta2) {
    int wid = threadIdx.x >> 5, lane = threadIdx.x & 31;
    int n = blockIdx.x * 8 + wid;
    if (n >= NN) return;

    int cnt = d_cursor[n];
    if (cnt > SLOT) cnt = SLOT;
    float loopv = d_loopsum[n] / fmaxf((float)cnt, 1.f);
    // reset adjacency state for next graph replay
    if (lane == 0) { d_cursor[n] = 0; d_loopsum[n] = 0.f; }

    int c0 = lane * 4;
    float4 xrv = *(const float4*)(d_xr2 + (size_t)n * 128 + c0);
    float4 w  = __ldg((const float4*)(We + c0));
    float4 at = __ldg((const float4*)(att + c0));

    float m = -1e30f, dsum = 0.f;
    float4 acc = make_float4(0.f, 0.f, 0.f, 0.f);

    const size_t sbase = (size_t)n * SLOT;
    int srcN; float eaN;
    if (cnt > 0) {
        u64 p = d_sadj[sbase];
        srcN = (int)(u32)p; eaN = __uint_as_float((u32)(p >> 32));
    } else { srcN = n; eaN = loopv; }
    float4 l_n = *(const float4*)(d_xl2 + (size_t)srcN * 128 + c0);
    float eav_n = eaN;

    for (int i = 0; i <= cnt; i++) {
        float4 l = l_n; float eav = eav_n;
        int j = i + 1;
        if (j <= cnt) {
            int s2; float e2;
            if (j < cnt) {
                u64 p = d_sadj[sbase + j];
                s2 = (int)(u32)p; e2 = __uint_as_float((u32)(p >> 32));
            } else { s2 = n; e2 = loopv; }
            l_n = *(const float4*)(d_xl2 + (size_t)s2 * 128 + c0);
            eav_n = e2;
        }
        float a = 0.f;
        a += gat_term(l.x, xrv.x, w.x, at.x, eav);
        a += gat_term(l.y, xrv.y, w.y, at.y, eav);
        a += gat_term(l.z, xrv.z, w.z, at.z, eav);
        a += gat_term(l.w, xrv.w, w.w, at.w, eav);
#pragma unroll
        for (int d = 1; d < 32; d <<= 1) a += __shfl_xor_sync(0xffffffffu, a, d);
        float nm = fmaxf(m, a);
        float sc = __expf(m - nm);
        float e  = __expf(a - nm);
        dsum = dsum * sc + e;
        m = nm;
        acc.x = acc.x * sc + e * l.x;
        acc.y = acc.y * sc + e * l.y;
        acc.z = acc.z * sc + e * l.z;
        acc.w = acc.w * sc + e * l.w;
    }

    float inv = 1.f / (dsum + 1e-16f);
    float4 bb = __ldg((const float4*)(b2 + c0));
    float o[4];
    o[0] = acc.x * inv + bb.x; o[1] = acc.y * inv + bb.y;
    o[2] = acc.z * inv + bb.z; o[3] = acc.w * inv + bb.w;

    float s = 0.f, s2v = 0.f;
#pragma unroll
    for (int j = 0; j < 4; j++) { s += o[j]; s2v += o[j] * o[j]; }
#pragma unroll
    for (int d = 16; d >= 1; d >>= 1) {
        s   += __shfl_xor_sync(0xffffffffu, s, d);
        s2v += __shfl_xor_sync(0xffffffffu, s2v, d);
    }
    float mu = s * (1.f / 128.f);
    float var = s2v * (1.f / 128.f) - mu * mu;
    float rstd = rsqrtf(var + 1e-5f);
    float4 gg = __ldg((const float4*)(g2 + c0));
    float4 tt = __ldg((const float4*)(beta2 + c0));
    float y0 = (o[0]-mu)*rstd*gg.x + tt.x;
    float y1 = (o[1]-mu)*rstd*gg.y + tt.y;
    float y2 = (o[2]-mu)*rstd*gg.z + tt.z;
    float y3 = (o[3]-mu)*rstd*gg.w + tt.w;
    y0 = (y0 > 0.f) ? y0 : (__expf(y0) - 1.f);
    y1 = (y1 > 0.f) ? y1 : (__expf(y1) - 1.f);
    y2 = (y2 > 0.f) ? y2 : (__expf(y2) - 1.f);
    y3 = (y3 > 0.f) ? y3 : (__expf(y3) - 1.f);
    *(float4*)(d_h2 + (size_t)n * 128 + c0) = make_float4(y0, y1, y2, y3);
}

// pooling: block of 128 threads handles 32 consecutive nodes (batch is sorted)
__global__ void k_pool(const int* __restrict__ batch) {
    __shared__ int s_b[32];
    int n0 = blockIdx.x * 32;
    int tid = threadIdx.x;
    if (tid < 32) {
        int n = n0 + tid;
        s_b[tid] = (n < NN) ? batch[n] : -1;
    }
    __syncthreads();
    int c = tid;
    float acc = 0.f;
    int cur = s_b[0];
    for (int j = 0; j < 32; j++) {
        int n = n0 + j;
        if (n >= NN) break;
        int g = s_b[j];
        if (g != cur) {
            atomicAdd(&d_pool[cur * 128 + c], acc);
            acc = 0.f;
            cur = g;
        }
        acc += d_h2[(size_t)n * 128 + c];
    }
    atomicAdd(&d_pool[cur * 128 + c], acc);
    if (tid == 0) {
        int cg = s_b[0];
        float ct = 0.f;
        for (int j = 0; j < 32; j++) {
            int n = n0 + j;
            if (n >= NN) break;
            int g = s_b[j];
            if (g != cg) { atomicAdd(&d_cnt[cg], ct); ct = 0.f; cg = g; }
            ct += 1.f;
        }
        atomicAdd(&d_cnt[cg], ct);
    }
}

__global__ void k_pooldiv(float* __restrict__ out) {
    int g = blockIdx.x, c = threadIdx.x;
    out[g * 128 + c] = d_pool[g * 128 + c] / fmaxf(d_cnt[g], 1.f);
    d_pool[g * 128 + c] = 0.f;      // reset for next replay
    if (c == 0) d_cnt[g] = 0.f;
}

// ---------------------------------------------------------------------------
extern "C" void kernel_launch(void* const* d_in, const int* in_sizes, int n_in,
                              void* d_out, int out_size) {
    const float* x     = (const float*)d_in[0];
    const int*   ei    = (const int*)  d_in[1];
    const float* ea    = (const float*)d_in[2];
    const int*   batch = (const int*)  d_in[3];
    const float* Wl1   = (const float*)d_in[4];
    const float* Wr1   = (const float*)d_in[5];
    const float* We1   = (const float*)d_in[6];
    const float* att1  = (const float*)d_in[7];
    const float* b1    = (const float*)d_in[8];
    const float* g1    = (const float*)d_in[9];
    const float* beta1 = (const float*)d_in[10];
    const float* Wl2   = (const float*)d_in[11];
    const float* Wr2   = (const float*)d_in[12];
    const float* We2   = (const float*)d_in[13];
    const float* att2  = (const float*)d_in[14];
    const float* b2    = (const float*)d_in[15];
    const float* g2    = (const float*)d_in[16];
    const float* beta2 = (const float*)d_in[17];
    float* out = (float*)d_out;

    k_gemm1<<<NN / 4, 256>>>(x, Wl1);                                 // #1
    k_fill<<<(NE / 2 + 255) / 256, 256>>>(ei, ea, 0, NE / 2);         // #2
    k_fill<<<(NE / 2 + 255) / 256, 256>>>(ei, ea, NE / 2, NE);        // #3
    k_fagg1<<<(NN + 7) / 8, 256>>>(x, Wr1, We1, att1, b1, g1, beta1); // #4 (profiled)
    k_gemm2<<<(NN + 127) / 128, 512>>>(Wl2, Wr2);                     // #5
    k_fagg2<<<(NN + 7) / 8, 256>>>(We2, att2, b2, g2, beta2);         // #6
    k_pool<<<(NN + 31) / 32, 128>>>(batch);                           // #7
    k_pooldiv<<<NG, 128>>>(out);                                      // #8
}